// round 7
// baseline (speedup 1.0000x reference)
#include <cuda_runtime.h>

#define VIEWS 512
#define DETS  512
#define H_IMG 256
#define W_IMG 256

// ---- constants (computed in double, used as float) ----
static constexpr double dPI     = 3.14159265358979323846;
static constexpr double dS2R    = 5.95;
static constexpr double dD2R    = 4.906;
static constexpr double dD_DET  = 0.0072;
static constexpr double dVIRDET = dD_DET * dS2R / (dS2R + dD2R);
static constexpr double dD_IMG  = 0.006641;
static constexpr double dD_ANG  = 2.0 * dPI / (double)VIEWS;

// filtered sinogram scratch: row = b*VIEWS + v, col = det
static __device__ float g_filtered[2 * VIEWS * DETS];

// ============================================================================
// Kernel 1: weight + ramp filter.
// Ramp filter is nonzero only at the center tap and odd offsets (even filt
// indices). With Ge[n] = filt[2n], Gp[n] = (Ge[n-1], Ge[n]):
//   even j=2a   : sum_s q[2s+1] * Gp[256+s-a].y
//   odd  j=2a+1 : sum_s q[2s]   * Gp[256+s-a].x
// plus center tap fc = filt[511].
// 128 blocks x 512 threads. Block covers 8 rows x all 512 outputs.
// Thread tile: 8 rows x 2 a-values (jt, jt+128) x 2 parities over one
// s-QUARTER (64 iters) -> 32 FMA per 10 LDS.64 in the inner loop.
// Partial sums combined via a 2-round conflict-free smem reduction.
// ============================================================================
__global__ __launch_bounds__(512)
void filter_kernel(const float* __restrict__ proj,
                   const float* __restrict__ w,
                   const float* __restrict__ filt) {
    __shared__ float  q[8][DETS];          // 16 KB (kept for center tap)
    __shared__ float2 Gp[DETS];            //  4 KB
    __shared__ float  red[2][32][128];     // 32 KB reduction buffer

    const int tid  = threadIdx.x;
    const int row0 = blockIdx.x * 8;

    {   // paired compressed tap table
        const int n = tid & 511;
        if (tid < 512) {
            float ge = filt[2 * n];
            float gm = (n >= 1) ? filt[2 * n - 2] : 0.0f;
            Gp[n] = make_float2(gm, ge);
        }
    }
    for (int idx = tid; idx < 8 * DETS; idx += 512) {
        int r = idx >> 9;
        int c = idx & (DETS - 1);
        q[r][c] = proj[(row0 + r) * DETS + c] * w[c];
    }
    __syncthreads();

    const int jt = tid & 127;    // output a-base: a0 = jt, a1 = jt + 128
    const int sg = tid >> 7;     // s-quarter [0,4)

    // acc[r][0]=E0, [1]=O0, [2]=E1, [3]=O1
    float acc[8][4];
#pragma unroll
    for (int r = 0; r < 8; ++r)
#pragma unroll
        for (int k = 0; k < 4; ++k) acc[r][k] = 0.0f;

    const float2* g0p = Gp + (256 - jt);   // for a0
    const float2* g1p = Gp + (128 - jt);   // for a1
    const int s0 = sg * 64;

#pragma unroll 2
    for (int ss = 0; ss < 64; ++ss) {
        const int s = s0 + ss;
        const float2 g0 = g0p[s];          // consecutive lanes -> conflict-free
        const float2 g1 = g1p[s];
#pragma unroll
        for (int r = 0; r < 8; ++r) {
            const float2 qv = *(const float2*)&q[r][2 * s];   // broadcast
            acc[r][0] = fmaf(qv.y, g0.y, acc[r][0]);
            acc[r][1] = fmaf(qv.x, g0.x, acc[r][1]);
            acc[r][2] = fmaf(qv.y, g1.y, acc[r][2]);
            acc[r][3] = fmaf(qv.x, g1.x, acc[r][3]);
        }
    }

    // ---- reduction across the 4 s-quarters (layout: red[b][k][jt]) ----
    if (sg == 1) {
#pragma unroll
        for (int k = 0; k < 32; ++k) red[0][k][jt] = acc[k >> 2][k & 3];
    } else if (sg == 3) {
#pragma unroll
        for (int k = 0; k < 32; ++k) red[1][k][jt] = acc[k >> 2][k & 3];
    }
    __syncthreads();
    if (sg == 0) {
#pragma unroll
        for (int k = 0; k < 32; ++k) acc[k >> 2][k & 3] += red[0][k][jt];
    } else if (sg == 2) {
#pragma unroll
        for (int k = 0; k < 32; ++k) acc[k >> 2][k & 3] += red[1][k][jt];
    }
    __syncthreads();
    if (sg == 2) {
#pragma unroll
        for (int k = 0; k < 32; ++k) red[0][k][jt] = acc[k >> 2][k & 3];
    }
    __syncthreads();

    if (sg == 0) {
        const float fc = filt[511];        // center tap
        const int j0 = 2 * jt;
        const int j1 = 2 * jt + 256;
#pragma unroll
        for (int r = 0; r < 8; ++r) {
            float e0 = acc[r][0] + red[0][4 * r + 0][jt];
            float o0 = acc[r][1] + red[0][4 * r + 1][jt];
            float e1 = acc[r][2] + red[0][4 * r + 2][jt];
            float o1 = acc[r][3] + red[0][4 * r + 3][jt];
            e0 = fmaf(fc, q[r][j0],     e0);
            o0 = fmaf(fc, q[r][j0 + 1], o0);
            e1 = fmaf(fc, q[r][j1],     e1);
            o1 = fmaf(fc, q[r][j1 + 1], o1);
            *(float2*)&g_filtered[(row0 + r) * DETS + j0] = make_float2(e0, o0);
            *(float2*)&g_filtered[(row0 + r) * DETS + j1] = make_float2(e1, o1);
        }
    }
}

// ============================================================================
// Kernel 2: fan-beam back-projection with half-turn symmetry.
// View pair (v, v+256): geometry at pixel (x,y) for v equals geometry at
// point-mirrored pixel (255-x, 255-y) for v+256 -> one geometry eval serves
// 2 views x 2 batches.
// Duplicated-pair gather table fr2[row][k] = (f[k], f[k+1]) zero-padded to
// 1024 (bias +383.5) -> each bilinear gather is ONE LDS.64, no masks.
// One pixel per lane (consecutive x) -> minimal j-spread -> minimal LDS
// replays; all 4 stores coalesced STG.32 (mirror warp reversed in-segment).
// Grid: (8 y-tiles, 256 view-pairs), 256 threads = one x each.
// ============================================================================
__global__ __launch_bounds__(256)
void backproject_kernel(float* __restrict__ out) {
    __shared__ float2 fr2[4][1024];   // 32 KB

    const int tid = threadIdx.x;      // x
    const int yt  = blockIdx.x;       // y tile [0,8)
    const int vp  = blockIdx.y;       // view pair: v0 = vp, v1 = vp + 256

    // pass 1: plain values into .x  (row order: v0b0, v0b1, v1b0, v1b1)
    for (int idx = tid; idx < 4096; idx += 256) {
        const int row = idx >> 10;
        const int col = idx & 1023;
        const int vi  = row >> 1;
        const int b   = row & 1;
        const int c   = col - 128;
        float val = 0.0f;
        if ((unsigned)c < (unsigned)DETS)
            val = g_filtered[(b * VIEWS + vp + vi * 256) * DETS + c];
        fr2[row][col].x = val;
    }
    __syncthreads();
    // pass 2: neighbor into .y
    for (int idx = tid; idx < 4096; idx += 256) {
        const int row = idx >> 10;
        const int col = idx & 1023;
        fr2[row][col].y = (col < 1023) ? fr2[row][col + 1].x : 0.0f;
    }

    const float beta = (float)dD_ANG * (float)vp;
    float sb, cb;
    sincosf(beta, &sb, &cb);
    __syncthreads();

    const float S2R  = (float)dS2R;
    const float DIMG = (float)dD_IMG;
    const float K    = (float)(dS2R / dVIRDET);
    const float Kcb  = K * cb;

    const float xs = ((float)tid - 127.5f) * DIMG;
    const float A  = S2R - xs * cb;        // d = A - ys*sb
    const float B  = K * (xs * sb);        // num = ys*Kcb - B

    const int ybase = yt * 32;
    const int bstr  = VIEWS * H_IMG * W_IMG;

    float* p0 = out + ((vp)       * H_IMG + ybase)         * W_IMG + tid;
    float* pm = out + ((vp + 256) * H_IMG + (255 - ybase)) * W_IMG + (255 - tid);

#pragma unroll 4
    for (int yy = 0; yy < 32; ++yy) {
        const float ys    = (127.5f - (float)(ybase + yy)) * DIMG;

        const float d   = A - ys * sb;
        const float inv = __fdividef(1.0f, d);
        const float t   = fmaf(ys * Kcb - B, inv, 383.5f);  // +255.5 +128 pad
        float wg = S2R * inv;  wg *= wg;

        const float fl = floorf(t);
        const float h  = t - fl;
        const int   j  = (int)fl;                           // in [3, 763]

        const float2 g0 = fr2[0][j];   // (f[j], f[j+1]) in one LDS.64
        const float2 g1 = fr2[1][j];
        const float2 g2 = fr2[2][j];
        const float2 g3 = fr2[3][j];

        p0[0]    = wg * fmaf(h, g0.y - g0.x, g0.x);   // view0 b0
        p0[bstr] = wg * fmaf(h, g1.y - g1.x, g1.x);   // view0 b1
        pm[0]    = wg * fmaf(h, g2.y - g2.x, g2.x);   // view1 b0 (mirrored)
        pm[bstr] = wg * fmaf(h, g3.y - g3.x, g3.x);   // view1 b1 (mirrored)

        p0 += W_IMG;
        pm -= W_IMG;
    }
}

extern "C" void kernel_launch(void* const* d_in, const int* in_sizes, int n_in,
                              void* d_out, int out_size) {
    const float* proj = (const float*)d_in[0];   // (2,1,512,512)
    const float* w    = (const float*)d_in[1];   // (1,1,1,512)
    const float* filt = (const float*)d_in[2];   // (1,1,1,1023)
    float* out = (float*)d_out;                  // (2,512,256,256)

    filter_kernel<<<128, 512>>>(proj, w, filt);
    backproject_kernel<<<dim3(8, 256), 256>>>(out);
}

// round 8
// speedup vs baseline: 1.4132x; 1.4132x over previous
#include <cuda_runtime.h>

#define VIEWS 512
#define DETS  512
#define H_IMG 256
#define W_IMG 256

// ---- constants (computed in double, used as float) ----
static constexpr double dPI     = 3.14159265358979323846;
static constexpr double dS2R    = 5.95;
static constexpr double dD2R    = 4.906;
static constexpr double dD_DET  = 0.0072;
static constexpr double dVIRDET = dD_DET * dS2R / (dS2R + dD2R);
static constexpr double dD_IMG  = 0.006641;
static constexpr double dD_ANG  = 2.0 * dPI / (double)VIEWS;

// filtered sinogram scratch: row = b*VIEWS + v, col = det
static __device__ float g_filtered[2 * VIEWS * DETS];

// packed f32x2 fma: (lo,hi) lanes independent
__device__ __forceinline__ unsigned long long fma2(unsigned long long a,
                                                   unsigned long long b,
                                                   unsigned long long c) {
    unsigned long long d;
    asm("fma.rn.f32x2 %0, %1, %2, %3;" : "=l"(d) : "l"(a), "l"(b), "l"(c));
    return d;
}

__device__ __forceinline__ float2 unpack2(unsigned long long v) {
    float2 r;
    asm("mov.b64 {%0, %1}, %2;" : "=f"(r.x), "=f"(r.y) : "l"(v));
    return r;
}

// ============================================================================
// Kernel 1: weight + ramp filter (FFMA2 + 16B-load version).
// Ramp filter is nonzero only at the center tap and odd offsets (even filt
// indices). With Ge[n] = filt[2n], iteration index n = 256 - a + s:
//   odd  j=2a+1 : accO += q[2s]   * Ge[n-1]
//   even j=2a   : accE += q[2s+1] * Ge[n]
// Both lines are ONE packed f32x2 FMA: (O,E) += (q[2s],q[2s+1])*(Ge[n-1],Ge[n])
// Tap quad table Gq[n] = (Ge[n-1], Ge[n], Ge[n], Ge[n+1]) is 16B-aligned at
// every n, so one LDS.128 provides the packed pairs for iters s and s+1.
// q rows read as LDS.128 broadcasts (2 iters per load).
// 128 blocks x 256 thr: jt in [0,128) -> a0 = jt, a1 = jt+128 (covers all j);
// rowgroup (tid>>7) x 4 rows. Inner chunk: 6 LDS + 16 FFMA2 per 2 s-iters.
// ============================================================================
__global__ __launch_bounds__(256)
void filter_kernel(const float* __restrict__ proj,
                   const float* __restrict__ w,
                   const float* __restrict__ filt) {
    __shared__ __align__(16) float  q[8][DETS];   // 16 KB
    __shared__ __align__(16) float4 Gq[DETS];     //  8 KB

    const int tid  = threadIdx.x;
    const int row0 = blockIdx.x * 8;

    for (int n = tid; n < DETS; n += 256) {
        float gm = (n >= 1)   ? filt[2 * n - 2] : 0.0f;   // Ge[n-1]
        float ge = filt[2 * n];                            // Ge[n]
        float gp = (n <= 510) ? filt[2 * n + 2] : 0.0f;   // Ge[n+1]
        Gq[n] = make_float4(gm, ge, ge, gp);
    }
    for (int idx = tid; idx < 8 * DETS; idx += 256) {
        int r = idx >> 9;
        int c = idx & (DETS - 1);
        q[r][c] = proj[(row0 + r) * DETS + c] * w[c];
    }
    __syncthreads();

    const int jt   = tid & 127;
    const int rowb = (tid >> 7) * 4;
    const int gi0  = 256 - jt;      // iter n = gi0 + s   (a0 = jt)
    const int gi1  = 128 - jt;      // iter n = gi1 + s   (a1 = jt + 128)

    unsigned long long acc[4][2];
#pragma unroll
    for (int r = 0; r < 4; ++r) { acc[r][0] = 0ull; acc[r][1] = 0ull; }

#pragma unroll 2
    for (int sp = 0; sp < 128; ++sp) {
        // taps for iters s=2sp and s=2sp+1, both a-values
        const ulonglong2 g0 = *(const ulonglong2*)&Gq[gi0 + 2 * sp];
        const ulonglong2 g1 = *(const ulonglong2*)&Gq[gi1 + 2 * sp];
#pragma unroll
        for (int r = 0; r < 4; ++r) {
            const ulonglong2 qv = *(const ulonglong2*)&q[rowb + r][4 * sp];
            acc[r][0] = fma2(qv.x, g0.x, acc[r][0]);
            acc[r][0] = fma2(qv.y, g0.y, acc[r][0]);
            acc[r][1] = fma2(qv.x, g1.x, acc[r][1]);
            acc[r][1] = fma2(qv.y, g1.y, acc[r][1]);
        }
    }

    const float fc = filt[511];     // center tap
    const int j0 = 2 * jt;
    const int j1 = 2 * jt + 256;
#pragma unroll
    for (int r = 0; r < 4; ++r) {
        float2 oe0 = unpack2(acc[r][0]);   // (O, E) for j0
        float2 oe1 = unpack2(acc[r][1]);   // (O, E) for j1
        float e0 = fmaf(fc, q[rowb + r][j0],     oe0.y);
        float o0 = fmaf(fc, q[rowb + r][j0 + 1], oe0.x);
        float e1 = fmaf(fc, q[rowb + r][j1],     oe1.y);
        float o1 = fmaf(fc, q[rowb + r][j1 + 1], oe1.x);
        *(float2*)&g_filtered[(row0 + rowb + r) * DETS + j0] = make_float2(e0, o0);
        *(float2*)&g_filtered[(row0 + rowb + r) * DETS + j1] = make_float2(e1, o1);
    }
}

// ============================================================================
// Kernel 2: fan-beam back-projection with half-turn symmetry (R2 version,
// measured 49.2us). View pair (v, v+256): geometry at (x,y) for v equals
// geometry at point-mirrored pixel for v+256. Filtered rows in smem padded
// to 1024 with zero borders (bias +383.5) -> no validity masks.
// Grid: (8 y-tiles, 256 view-pairs), 256 thr = 128 x-pairs x 2 y-offsets.
// 4x STG.64 per iteration, scalar LDS gathers.
// ============================================================================
__global__ __launch_bounds__(256)
void backproject_kernel(float* __restrict__ out) {
    __shared__ float fr[4][1024];   // 16 KB

    const int tid = threadIdx.x;
    const int tx  = tid & 127;      // x-pair: x0 = 2tx, x1 = 2tx+1
    const int ty  = tid >> 7;       // y offset within row pair
    const int yt  = blockIdx.x;     // y-tile [0,8)
    const int vp  = blockIdx.y;     // view pair: v0 = vp, v1 = vp + 256

    for (int idx = tid; idx < 4096; idx += 256) {
        const int row = idx >> 10;
        const int col = idx & 1023;
        const int vi  = row >> 1;
        const int b   = row & 1;
        const int c   = col - 128;
        float val = 0.0f;
        if ((unsigned)c < (unsigned)DETS)
            val = g_filtered[(b * VIEWS + vp + vi * 256) * DETS + c];
        fr[row][col] = val;
    }

    const float beta = (float)dD_ANG * (float)vp;
    float sb, cb;
    sincosf(beta, &sb, &cb);
    __syncthreads();

    const float S2R  = (float)dS2R;
    const float DIMG = (float)dD_IMG;
    const float K    = (float)(dS2R / dVIRDET);
    const float Kcb  = K * cb;

    const float xs0 = (2.0f * (float)tx - 127.5f) * DIMG;
    const float xs1 = xs0 + DIMG;
    const float A0  = S2R - xs0 * cb;      // d = A - ys*sb
    const float A1  = S2R - xs1 * cb;
    const float B0  = K * (xs0 * sb);      // num = ys*Kcb - B
    const float B1  = K * (xs1 * sb);

    const int ybase = yt * 32;
    const int bstr  = VIEWS * H_IMG * W_IMG;

    float* p0 = out + ((vp)       * H_IMG + (ybase + ty))       * W_IMG + 2 * tx;
    float* pm = out + ((vp + 256) * H_IMG + (255 - ybase - ty)) * W_IMG + (254 - 2 * tx);

#pragma unroll 4
    for (int i = 0; i < 16; ++i) {
        const float yv    = (float)(ybase + 2 * i + ty);
        const float ys    = (127.5f - yv) * DIMG;
        const float yssb  = ys * sb;
        const float ysKcb = ys * Kcb;

        const float d0   = A0 - yssb;
        const float d1   = A1 - yssb;
        const float inv0 = __fdividef(1.0f, d0);
        const float inv1 = __fdividef(1.0f, d1);
        const float t0   = fmaf(ysKcb - B0, inv0, 383.5f);   // +255.5 +128 pad
        const float t1   = fmaf(ysKcb - B1, inv1, 383.5f);
        float wg0 = S2R * inv0; wg0 *= wg0;
        float wg1 = S2R * inv1; wg1 *= wg1;

        const float f0 = floorf(t0);
        const float f1 = floorf(t1);
        const float h0 = t0 - f0;
        const float h1 = t1 - f1;
        const int   j0 = (int)f0;
        const int   j1 = (int)f1;

        float a00 = fr[0][j0], b00 = fr[0][j0 + 1];
        float a01 = fr[1][j0], b01 = fr[1][j0 + 1];
        float a02 = fr[2][j0], b02 = fr[2][j0 + 1];
        float a03 = fr[3][j0], b03 = fr[3][j0 + 1];
        float a10 = fr[0][j1], b10 = fr[0][j1 + 1];
        float a11 = fr[1][j1], b11 = fr[1][j1 + 1];
        float a12 = fr[2][j1], b12 = fr[2][j1 + 1];
        float a13 = fr[3][j1], b13 = fr[3][j1 + 1];

        const float v00x0 = wg0 * fmaf(h0, b00 - a00, a00);  // view0 b0 x0
        const float v01x0 = wg0 * fmaf(h0, b01 - a01, a01);  // view0 b1 x0
        const float v10x0 = wg0 * fmaf(h0, b02 - a02, a02);  // view1 b0 x0
        const float v11x0 = wg0 * fmaf(h0, b03 - a03, a03);  // view1 b1 x0
        const float v00x1 = wg1 * fmaf(h1, b10 - a10, a10);
        const float v01x1 = wg1 * fmaf(h1, b11 - a11, a11);
        const float v10x1 = wg1 * fmaf(h1, b12 - a12, a12);
        const float v11x1 = wg1 * fmaf(h1, b13 - a13, a13);

        *(float2*)(p0)        = make_float2(v00x0, v00x1);
        *(float2*)(p0 + bstr) = make_float2(v01x0, v01x1);
        // mirrored view: x reversed -> swap components
        *(float2*)(pm)        = make_float2(v10x1, v10x0);
        *(float2*)(pm + bstr) = make_float2(v11x1, v11x0);

        p0 += 2 * W_IMG;
        pm -= 2 * W_IMG;
    }
}

extern "C" void kernel_launch(void* const* d_in, const int* in_sizes, int n_in,
                              void* d_out, int out_size) {
    const float* proj = (const float*)d_in[0];   // (2,1,512,512)
    const float* w    = (const float*)d_in[1];   // (1,1,1,512)
    const float* filt = (const float*)d_in[2];   // (1,1,1,1023)
    float* out = (float*)d_out;                  // (2,512,256,256)

    filter_kernel<<<128, 256>>>(proj, w, filt);
    backproject_kernel<<<dim3(8, 256), 256>>>(out);
}

// round 9
// speedup vs baseline: 1.5002x; 1.0616x over previous
#include <cuda_runtime.h>

#define VIEWS 512
#define DETS  512
#define H_IMG 256
#define W_IMG 256

// ---- constants (computed in double, used as float) ----
static constexpr double dPI     = 3.14159265358979323846;
static constexpr double dS2R    = 5.95;
static constexpr double dD2R    = 4.906;
static constexpr double dD_DET  = 0.0072;
static constexpr double dVIRDET = dD_DET * dS2R / (dS2R + dD2R);
static constexpr double dD_IMG  = 0.006641;
static constexpr double dD_ANG  = 2.0 * dPI / (double)VIEWS;

// packed f32x2 fma: (lo,hi) lanes independent
__device__ __forceinline__ unsigned long long fma2(unsigned long long a,
                                                   unsigned long long b,
                                                   unsigned long long c) {
    unsigned long long d;
    asm("fma.rn.f32x2 %0, %1, %2, %3;" : "=l"(d) : "l"(a), "l"(b), "l"(c));
    return d;
}

__device__ __forceinline__ float2 unpack2(unsigned long long v) {
    float2 r;
    asm("mov.b64 {%0, %1}, %2;" : "=f"(r.x), "=f"(r.y) : "l"(v));
    return r;
}

// ============================================================================
// Fused per-view-pair kernel. Grid: 256 blocks (one per view pair vp,
// v0 = vp, v1 = vp + 256), 256 threads. One launch, no global scratch.
//
// Phase 1 (filter): block filters its own 4 sinogram rows (2 views x 2
// batches) directly into the smem gather table.
//   Ramp filter nonzero only at center tap + odd offsets (even filt indices).
//   Ge[n] = filt[2n]; tap quad Gq[n] = (Ge[n-1],Ge[n],Ge[n],Ge[n+1]) is
//   16B-aligned at every n so one LDS.128 yields packed (O,E) tap pairs for
//   two s-iterations. q rows read as LDS.128 broadcasts.
//   Thread (jt = tid&127, vi = tid>>7): both batches of view vi, outputs
//   j0 = 2jt(+1), j1 = 2jt+256(+1). Inner chunk (2 s-iters): 2 spread
//   LDS.128 + 2 broadcast LDS.128 + 8 FFMA2.
//   Output table frB[vi][col] = float2(batch0, batch1), zero-padded to 1024
//   cols (bias +383.5) so backprojection needs no validity masks.
//
// Phase 2 (backproject): half-turn symmetry — geometry at (x,y) for v0
// equals geometry at point-mirrored pixel for v1. 128 x-pairs x 2 ty.
// Per iteration: 2 geometries, 8 outputs, 8 LDS.64 gathers, 4 STG.64.
// ============================================================================
__global__ __launch_bounds__(256)
void fbp_kernel(const float* __restrict__ proj,
                const float* __restrict__ w,
                const float* __restrict__ filt,
                float* __restrict__ out) {
    __shared__ __align__(16) float  q[4][DETS];    //  8 KB  [b*2+vi][c]
    __shared__ __align__(16) float4 Gq[DETS];      //  8 KB
    __shared__ __align__(16) float2 frB[2][1024];  // 16 KB  [vi][pad col]

    const int tid = threadIdx.x;
    const int vp  = blockIdx.x;          // v0 = vp, v1 = vp + 256

    // ---- load tap table + weighted sinogram rows ----
    for (int n = tid; n < DETS; n += 256) {
        float gm = (n >= 1)   ? filt[2 * n - 2] : 0.0f;   // Ge[n-1]
        float ge = filt[2 * n];                            // Ge[n]
        float gp = (n <= 510) ? filt[2 * n + 2] : 0.0f;   // Ge[n+1]
        Gq[n] = make_float4(gm, ge, ge, gp);
    }
    for (int idx = tid; idx < 4 * DETS; idx += 256) {
        const int r = idx >> 9;          // r = b*2 + vi
        const int c = idx & (DETS - 1);
        const int b  = r >> 1;
        const int vi = r & 1;
        q[r][c] = proj[(b * VIEWS + vp + vi * 256) * DETS + c] * w[c];
    }
    // zero the pad regions of frB: cols [0,128) and [640,1024)
    for (int idx = tid; idx < 1024; idx += 256) {
        const int vi  = idx >> 9;
        const int k   = idx & 511;
        const int col = (k < 128) ? k : (512 + k);
        frB[vi][col] = make_float2(0.0f, 0.0f);
    }
    __syncthreads();

    // ---- Phase 1: ramp filter ----
    {
        const int jt  = tid & 127;
        const int vi  = tid >> 7;
        const int gi0 = 256 - jt;        // iter n = gi0 + s  (a0 = jt)
        const int gi1 = 128 - jt;        // iter n = gi1 + s  (a1 = jt + 128)

        // acc[b][a] packed (O, E)
        unsigned long long acc[2][2];
        acc[0][0] = acc[0][1] = acc[1][0] = acc[1][1] = 0ull;

#pragma unroll 2
        for (int sp = 0; sp < 128; ++sp) {
            const ulonglong2 g0 = *(const ulonglong2*)&Gq[gi0 + 2 * sp];
            const ulonglong2 g1 = *(const ulonglong2*)&Gq[gi1 + 2 * sp];
            const ulonglong2 q0 = *(const ulonglong2*)&q[vi][4 * sp];      // b0
            const ulonglong2 q1 = *(const ulonglong2*)&q[2 + vi][4 * sp];  // b1

            acc[0][0] = fma2(q0.x, g0.x, acc[0][0]);
            acc[0][0] = fma2(q0.y, g0.y, acc[0][0]);
            acc[0][1] = fma2(q0.x, g1.x, acc[0][1]);
            acc[0][1] = fma2(q0.y, g1.y, acc[0][1]);
            acc[1][0] = fma2(q1.x, g0.x, acc[1][0]);
            acc[1][0] = fma2(q1.y, g0.y, acc[1][0]);
            acc[1][1] = fma2(q1.x, g1.x, acc[1][1]);
            acc[1][1] = fma2(q1.y, g1.y, acc[1][1]);
        }

        const float fc = filt[511];      // center tap
        const int j0 = 2 * jt;
        const int j1 = 2 * jt + 256;

        const float2 oe00 = unpack2(acc[0][0]);   // b0, j0: (O, E)
        const float2 oe01 = unpack2(acc[0][1]);   // b0, j1
        const float2 oe10 = unpack2(acc[1][0]);   // b1, j0
        const float2 oe11 = unpack2(acc[1][1]);   // b1, j1

        const float q0j0  = q[vi][j0],     q0j0p = q[vi][j0 + 1];
        const float q0j1  = q[vi][j1],     q0j1p = q[vi][j1 + 1];
        const float q1j0  = q[2 + vi][j0], q1j0p = q[2 + vi][j0 + 1];
        const float q1j1  = q[2 + vi][j1], q1j1p = q[2 + vi][j1 + 1];

        frB[vi][128 + j0]     = make_float2(fmaf(fc, q0j0,  oe00.y),
                                            fmaf(fc, q1j0,  oe10.y));
        frB[vi][128 + j0 + 1] = make_float2(fmaf(fc, q0j0p, oe00.x),
                                            fmaf(fc, q1j0p, oe10.x));
        frB[vi][128 + j1]     = make_float2(fmaf(fc, q0j1,  oe01.y),
                                            fmaf(fc, q1j1,  oe11.y));
        frB[vi][128 + j1 + 1] = make_float2(fmaf(fc, q0j1p, oe01.x),
                                            fmaf(fc, q1j1p, oe11.x));
    }

    const float beta = (float)dD_ANG * (float)vp;
    float sb, cb;
    sincosf(beta, &sb, &cb);
    __syncthreads();

    // ---- Phase 2: back-projection (half-turn symmetric view pair) ----
    const float S2R  = (float)dS2R;
    const float DIMG = (float)dD_IMG;
    const float K    = (float)(dS2R / dVIRDET);
    const float Kcb  = K * cb;

    const int tx = tid & 127;        // x-pair: x0 = 2tx, x1 = 2tx+1
    const int ty = tid >> 7;         // y offset within row pair

    const float xs0 = (2.0f * (float)tx - 127.5f) * DIMG;
    const float xs1 = xs0 + DIMG;
    const float A0  = S2R - xs0 * cb;      // d = A - ys*sb
    const float A1  = S2R - xs1 * cb;
    const float B0  = K * (xs0 * sb);      // num = ys*Kcb - B
    const float B1  = K * (xs1 * sb);

    const int bstr = VIEWS * H_IMG * W_IMG;

    float* p0 = out + ((vp)       * H_IMG + ty)         * W_IMG + 2 * tx;
    float* pm = out + ((vp + 256) * H_IMG + (255 - ty)) * W_IMG + (254 - 2 * tx);

#pragma unroll 4
    for (int i = 0; i < 128; ++i) {
        const float yv    = (float)(2 * i + ty);
        const float ys    = (127.5f - yv) * DIMG;
        const float yssb  = ys * sb;
        const float ysKcb = ys * Kcb;

        const float d0   = A0 - yssb;
        const float d1   = A1 - yssb;
        const float inv0 = __fdividef(1.0f, d0);
        const float inv1 = __fdividef(1.0f, d1);
        const float t0   = fmaf(ysKcb - B0, inv0, 383.5f);   // +255.5 +128 pad
        const float t1   = fmaf(ysKcb - B1, inv1, 383.5f);
        float wg0 = S2R * inv0; wg0 *= wg0;
        float wg1 = S2R * inv1; wg1 *= wg1;

        const float f0 = floorf(t0);
        const float f1 = floorf(t1);
        const float h0 = t0 - f0;
        const float h1 = t1 - f1;
        const int   j0 = (int)f0;
        const int   j1 = (int)f1;

        // batch-interleaved gathers: one LDS.64 per (view, tap)
        const float2 v0a = frB[0][j0],     v0b = frB[0][j0 + 1];   // view0 @x0
        const float2 v1a = frB[1][j0],     v1b = frB[1][j0 + 1];   // view1 @x0
        const float2 u0a = frB[0][j1],     u0b = frB[0][j1 + 1];   // view0 @x1
        const float2 u1a = frB[1][j1],     u1b = frB[1][j1 + 1];   // view1 @x1

        const float v00x0 = wg0 * fmaf(h0, v0b.x - v0a.x, v0a.x);  // v0 b0 x0
        const float v01x0 = wg0 * fmaf(h0, v0b.y - v0a.y, v0a.y);  // v0 b1 x0
        const float v10x0 = wg0 * fmaf(h0, v1b.x - v1a.x, v1a.x);  // v1 b0 x0
        const float v11x0 = wg0 * fmaf(h0, v1b.y - v1a.y, v1a.y);  // v1 b1 x0
        const float v00x1 = wg1 * fmaf(h1, u0b.x - u0a.x, u0a.x);
        const float v01x1 = wg1 * fmaf(h1, u0b.y - u0a.y, u0a.y);
        const float v10x1 = wg1 * fmaf(h1, u1b.x - u1a.x, u1a.x);
        const float v11x1 = wg1 * fmaf(h1, u1b.y - u1a.y, u1a.y);

        *(float2*)(p0)        = make_float2(v00x0, v00x1);
        *(float2*)(p0 + bstr) = make_float2(v01x0, v01x1);
        // mirrored view: x reversed -> swap components
        *(float2*)(pm)        = make_float2(v10x1, v10x0);
        *(float2*)(pm + bstr) = make_float2(v11x1, v11x0);

        p0 += 2 * W_IMG;
        pm -= 2 * W_IMG;
    }
}

extern "C" void kernel_launch(void* const* d_in, const int* in_sizes, int n_in,
                              void* d_out, int out_size) {
    const float* proj = (const float*)d_in[0];   // (2,1,512,512)
    const float* w    = (const float*)d_in[1];   // (1,1,1,512)
    const float* filt = (const float*)d_in[2];   // (1,1,1,1023)
    float* out = (float*)d_out;                  // (2,512,256,256)

    fbp_kernel<<<256, 256>>>(proj, w, filt, out);
}